// round 1
// baseline (speedup 1.0000x reference)
#include <cuda_runtime.h>
#include <cstdint>
#include <cstddef>

#define BATCH   2
#define LSEQ    2048
#define BL      4096
#define DMODEL  1024
#define DHALF   512
#define DINNER  1024
#define DSTATE  128
#define NH      16
#define HD      64
#define CONVDIM 1280
#define DPROJ   2320

// ---------------- scratch (static device memory; no allocations) ----------------
__device__ float g_u[2][BL][DHALF];     // rmsnorm halves (dir1 time-flipped)
__device__ float g_zx[2][BL][DPROJ];    // in-proj output: [z(1024) | xBC(1280) | dt(16)]
__device__ float g_xc[2][BL][CONVDIM];  // silu(conv): [x(1024) | B(128) | C(128)]
__device__ float g_dt[2][BL][NH];       // softplus(dt + bias)
__device__ float g_dA[2][BL][NH];       // exp(dt * A)
__device__ float g_y[2][BL][DINNER];    // scan output -> gated+normed in place
__device__ float g_od[BL][DMODEL];      // concat(out_f, flip(out_b))

// ---------------- K1: input RMSNorm + split + flip of backward half ----------------
__global__ __launch_bounds__(256) void k_rmsnorm_split(const float* __restrict__ x,
                                                       const float* __restrict__ norm_w) {
  int row = blockIdx.x;
  int tid = threadIdx.x;
  const float* xr = x + (size_t)row * DMODEL;
  float v[4];
  float ss = 0.f;
#pragma unroll
  for (int i = 0; i < 4; i++) { v[i] = xr[tid + i * 256]; ss += v[i] * v[i]; }
  __shared__ float red[256];
  red[tid] = ss;
  __syncthreads();
  for (int s = 128; s > 0; s >>= 1) {
    if (tid < s) red[tid] += red[tid + s];
    __syncthreads();
  }
  float scale = rsqrtf(red[0] * (1.f / DMODEL) + 1e-5f);
  int l = row & 2047;
  int rrow = (row & ~2047) + (2047 - l);
#pragma unroll
  for (int i = 0; i < 4; i++) {
    int c = tid + i * 256;
    float val = v[i] * scale * norm_w[c];
    if (c < DHALF) g_u[0][row][c] = val;
    else           g_u[1][rrow][c - DHALF] = val;
  }
}

// ---------------- K2: generic SGEMM  C[M,N] = A[M,K] @ W[N,K]^T (+bias)(+res) ----------------
// A row stride = K. Output written at C[orow*ldc + col_off + n], orow time-flipped if flip.
__global__ __launch_bounds__(256) void k_sgemm(
    const float* __restrict__ A, const float* __restrict__ W,
    const float* __restrict__ bias, const float* __restrict__ res,
    float* __restrict__ C, int M, int N, int K, int ldc, int col_off, int flip)
{
  __shared__ float As[16][132];
  __shared__ float Ws[16][132];
  int tid  = threadIdx.x;
  int row0 = blockIdx.y * 128, col0 = blockIdx.x * 128;
  int lr = tid >> 2;
  int lc = (tid & 3) << 2;
  int tx = tid & 15, ty = tid >> 4;
  float acc[8][8];
#pragma unroll
  for (int i = 0; i < 8; i++)
#pragma unroll
    for (int j = 0; j < 8; j++) acc[i][j] = 0.f;

  for (int k0 = 0; k0 < K; k0 += 16) {
#pragma unroll
    for (int s = 0; s < 2; s++) {
      int r = lr + s * 64;
      float4 av = *(const float4*)(A + (size_t)(row0 + r) * K + k0 + lc);
      As[lc + 0][r] = av.x; As[lc + 1][r] = av.y; As[lc + 2][r] = av.z; As[lc + 3][r] = av.w;
      int wr = col0 + r;
      float4 wv = make_float4(0.f, 0.f, 0.f, 0.f);
      if (wr < N) wv = *(const float4*)(W + (size_t)wr * K + k0 + lc);
      Ws[lc + 0][r] = wv.x; Ws[lc + 1][r] = wv.y; Ws[lc + 2][r] = wv.z; Ws[lc + 3][r] = wv.w;
    }
    __syncthreads();
#pragma unroll
    for (int kk = 0; kk < 16; kk++) {
      float a[8], bb[8];
#pragma unroll
      for (int i = 0; i < 8; i++) a[i] = As[kk][ty * 8 + i];
#pragma unroll
      for (int j = 0; j < 8; j++) bb[j] = Ws[kk][tx * 8 + j];
#pragma unroll
      for (int i = 0; i < 8; i++)
#pragma unroll
        for (int j = 0; j < 8; j++)
          acc[i][j] = fmaf(a[i], bb[j], acc[i][j]);
    }
    __syncthreads();
  }

#pragma unroll
  for (int i = 0; i < 8; i++) {
    int m = row0 + ty * 8 + i;
    int orow = m;
    if (flip) orow = (m & ~2047) + (2047 - (m & 2047));
#pragma unroll
    for (int j = 0; j < 8; j++) {
      int n = col0 + tx * 8 + j;
      if (n < N) {
        float v = acc[i][j];
        if (bias) v += bias[n];
        if (res)  v += res[(size_t)m * ldc + col_off + n];
        C[(size_t)orow * ldc + col_off + n] = v;
      }
    }
  }
}

// ---------------- K3: depthwise causal conv(4) + SiLU; softplus(dt), dA ----------------
__global__ __launch_bounds__(256) void k_conv(int dir,
    const float* __restrict__ conv_w, const float* __restrict__ conv_b,
    const float* __restrict__ dt_bias, const float* __restrict__ A_log)
{
  int row = blockIdx.x;
  int tid = threadIdx.x;
  int l  = row & 2047;
  int rb = row & ~2047;
  for (int c = tid; c < CONVDIM; c += 256) {
    float acc = conv_b[c];
#pragma unroll
    for (int k = 0; k < 4; k++) {
      int ls = l - 3 + k;
      if (ls >= 0) acc = fmaf(conv_w[c * 4 + k], g_zx[dir][rb + ls][DINNER + c], acc);
    }
    g_xc[dir][row][c] = acc / (1.f + expf(-acc));
  }
  if (tid < NH) {
    float d = g_zx[dir][row][DINNER + CONVDIM + tid] + dt_bias[tid];
    float sp = (d > 20.f) ? d : log1pf(expf(d));
    g_dt[dir][row][tid] = sp;
    g_dA[dir][row][tid] = expf(-sp * expf(A_log[tid]));
  }
}

// ---------------- K4: recurrent selective scan ----------------
// block = (b, head) for one dir; 512 threads: p = tid>>3 (0..63), g = tid&7.
// Each thread carries h[16] for n = g + 8*j (stride-8 swizzle: conflict-free LDS).
#define TT 32
__global__ __launch_bounds__(512) void k_scan(int dir, const float* __restrict__ Dvec)
{
  int b  = blockIdx.x >> 4;
  int hh = blockIdx.x & 15;
  int tid = threadIdx.x;
  int p = tid >> 3, g = tid & 7;
  __shared__ float sB[TT][DSTATE];
  __shared__ float sC[TT][DSTATE];
  __shared__ float sx[TT][HD];
  __shared__ float sdt[TT];
  __shared__ float sdA[TT];
  float h[16];
#pragma unroll
  for (int j = 0; j < 16; j++) h[j] = 0.f;
  float Dh = Dvec[hh];
  int rowbase = b << 11;

  for (int t0 = 0; t0 < LSEQ; t0 += TT) {
    __syncthreads();
    for (int i = tid; i < TT * DSTATE; i += 512) {
      int tt = i >> 7, n = i & 127;
      int row = rowbase + t0 + tt;
      sB[tt][n] = g_xc[dir][row][DINNER + n];
      sC[tt][n] = g_xc[dir][row][DINNER + DSTATE + n];
    }
    for (int i = tid; i < TT * HD; i += 512) {
      int tt = i >> 6, pp = i & 63;
      sx[tt][pp] = g_xc[dir][rowbase + t0 + tt][hh * HD + pp];
    }
    if (tid < TT) {
      sdt[tid] = g_dt[dir][rowbase + t0 + tid][hh];
      sdA[tid] = g_dA[dir][rowbase + t0 + tid][hh];
    }
    __syncthreads();
#pragma unroll 4
    for (int tt = 0; tt < TT; tt++) {
      float dA = sdA[tt];
      float s  = sdt[tt] * sx[tt][p];
      float acc = 0.f;
#pragma unroll
      for (int j = 0; j < 16; j++) {
        int n = g + (j << 3);
        h[j] = fmaf(dA, h[j], s * sB[tt][n]);
        acc  = fmaf(h[j], sC[tt][n], acc);
      }
      acc += __shfl_xor_sync(0xffffffffu, acc, 1);
      acc += __shfl_xor_sync(0xffffffffu, acc, 2);
      acc += __shfl_xor_sync(0xffffffffu, acc, 4);
      if (g == 0)
        g_y[dir][rowbase + t0 + tt][hh * HD + p] = acc + Dh * sx[tt][p];
    }
  }
}

// ---------------- K5: gating (y * silu(z)) + gated RMSNorm (in place) ----------------
__global__ __launch_bounds__(256) void k_gate(int dir, const float* __restrict__ gnorm_w)
{
  int row = blockIdx.x;
  int tid = threadIdx.x;
  float vals[4];
  float ss = 0.f;
#pragma unroll
  for (int i = 0; i < 4; i++) {
    int c = tid + i * 256;
    float yv = g_y[dir][row][c];
    float z  = g_zx[dir][row][c];
    float gv = yv * (z / (1.f + expf(-z)));
    vals[i] = gv;
    ss += gv * gv;
  }
  __shared__ float red[256];
  red[tid] = ss;
  __syncthreads();
  for (int s = 128; s > 0; s >>= 1) {
    if (tid < s) red[tid] += red[tid + s];
    __syncthreads();
  }
  float sc = rsqrtf(red[0] * (1.f / DINNER) + 1e-5f);
#pragma unroll
  for (int i = 0; i < 4; i++) {
    int c = tid + i * 256;
    g_y[dir][row][c] = vals[i] * sc * gnorm_w[c];
  }
}

// ---------------- launch ----------------
extern "C" void kernel_launch(void* const* d_in, const int* in_sizes, int n_in,
                              void* d_out, int out_size)
{
  (void)in_sizes; (void)n_in; (void)out_size;
  const float* x       = (const float*)d_in[0];
  const float* norm_w  = (const float*)d_in[1];
  const float* op_w    = (const float*)d_in[2];
  const float* op_b    = (const float*)d_in[3];
  const float* in_w[2]    = {(const float*)d_in[4],  (const float*)d_in[12]};
  const float* conv_w[2]  = {(const float*)d_in[5],  (const float*)d_in[13]};
  const float* conv_b[2]  = {(const float*)d_in[6],  (const float*)d_in[14]};
  const float* dt_bias[2] = {(const float*)d_in[7],  (const float*)d_in[15]};
  const float* A_log[2]   = {(const float*)d_in[8],  (const float*)d_in[16]};
  const float* Dvec[2]    = {(const float*)d_in[9],  (const float*)d_in[17]};
  const float* gnorm[2]   = {(const float*)d_in[10], (const float*)d_in[18]};
  const float* outp_w[2]  = {(const float*)d_in[11], (const float*)d_in[19]};
  float* out = (float*)d_out;

  float *pu, *pzx, *py, *pod;
  cudaGetSymbolAddress((void**)&pu,  g_u);
  cudaGetSymbolAddress((void**)&pzx, g_zx);
  cudaGetSymbolAddress((void**)&py,  g_y);
  cudaGetSymbolAddress((void**)&pod, g_od);

  k_rmsnorm_split<<<BL, 256>>>(x, norm_w);

  for (int d = 0; d < 2; d++) {
    k_sgemm<<<dim3((DPROJ + 127) / 128, BL / 128), 256>>>(
        pu + (size_t)d * BL * DHALF, in_w[d], nullptr, nullptr,
        pzx + (size_t)d * BL * DPROJ, BL, DPROJ, DHALF, DPROJ, 0, 0);
  }
  for (int d = 0; d < 2; d++)
    k_conv<<<BL, 256>>>(d, conv_w[d], conv_b[d], dt_bias[d], A_log[d]);

  for (int d = 0; d < 2; d++)
    k_scan<<<32, 512>>>(d, Dvec[d]);

  for (int d = 0; d < 2; d++)
    k_gate<<<BL, 256>>>(d, gnorm[d]);

  for (int d = 0; d < 2; d++)
    k_sgemm<<<dim3(DHALF / 128, BL / 128), 256>>>(
        py + (size_t)d * BL * DINNER, outp_w[d], nullptr, nullptr,
        pod, BL, DHALF, DINNER, DMODEL, d * DHALF, d);

  k_sgemm<<<dim3(DMODEL / 128, BL / 128), 256>>>(
      pod, op_w, op_b, x, out, BL, DMODEL, DMODEL, DMODEL, 0, 0);
}

// round 3
// speedup vs baseline: 2.2211x; 2.2211x over previous
#include <cuda_runtime.h>
#include <cstdint>
#include <cstddef>

#define BATCH   2
#define LSEQ    2048
#define BL      4096
#define DMODEL  1024
#define DHALF   512
#define DINNER  1024
#define DSTATE  128
#define NH      16
#define HD      64
#define CONVDIM 1280
#define DPROJ   2320

// ---------------- scratch ----------------
__device__ float g_u[2][BL][DHALF];
__device__ float g_zx[2][BL][DPROJ];
__device__ float g_xc[2][BL][CONVDIM];
__device__ float g_dt[2][BL][NH];
__device__ float g_dA[2][BL][NH];
__device__ float g_y[2][BL][DINNER];
__device__ float g_od[BL][DMODEL];

// ---------------- helpers ----------------
__device__ __forceinline__ void cp16(uint32_t dst, const float* src, int szbytes) {
  asm volatile("cp.async.cg.shared.global [%0], [%1], 16, %2;"
               :: "r"(dst), "l"(src), "r"(szbytes) : "memory");
}
#define CP_COMMIT() asm volatile("cp.async.commit_group;" ::: "memory")
#define CP_WAIT1()  asm volatile("cp.async.wait_group 1;" ::: "memory")
#define CP_WAIT0()  asm volatile("cp.async.wait_group 0;" ::: "memory")

__device__ __forceinline__ void mma1688(float* c, const uint32_t* a, const uint32_t* b) {
  asm volatile(
    "mma.sync.aligned.m16n8k8.row.col.f32.tf32.tf32.f32 "
    "{%0,%1,%2,%3}, {%4,%5,%6,%7}, {%8,%9}, {%0,%1,%2,%3};"
    : "+f"(c[0]), "+f"(c[1]), "+f"(c[2]), "+f"(c[3])
    : "r"(a[0]), "r"(a[1]), "r"(a[2]), "r"(a[3]), "r"(b[0]), "r"(b[1]));
}

// ---------------- K1: RMSNorm + split + flip ----------------
__global__ __launch_bounds__(256) void k_rmsnorm_split(const float* __restrict__ x,
                                                       const float* __restrict__ norm_w) {
  int row = blockIdx.x, tid = threadIdx.x;
  const float* xr = x + (size_t)row * DMODEL;
  float v[4]; float ss = 0.f;
#pragma unroll
  for (int i = 0; i < 4; i++) { v[i] = xr[tid + i * 256]; ss += v[i] * v[i]; }
  __shared__ float red[256];
  red[tid] = ss; __syncthreads();
  for (int s = 128; s > 0; s >>= 1) { if (tid < s) red[tid] += red[tid + s]; __syncthreads(); }
  float scale = rsqrtf(red[0] * (1.f / DMODEL) + 1e-5f);
  int l = row & 2047, rrow = (row & ~2047) + (2047 - l);
#pragma unroll
  for (int i = 0; i < 4; i++) {
    int c = tid + i * 256;
    float val = v[i] * scale * norm_w[c];
    if (c < DHALF) g_u[0][row][c] = val;
    else           g_u[1][rrow][c - DHALF] = val;
  }
}

// ---------------- K2: tf32 mma.sync GEMM  C = A[M,K] @ W[N,K]^T (+bias)(+res) ----------------
// 128x128x16 tile, 8 warps (2x4), each warp 64x32 via m16n8k8 frags.
#define TKS 16
#define SROW 20   // smem row stride in floats (16 data + 4 pad, conflict-free)
__global__ __launch_bounds__(256)
void k_gemm_mma(const float* __restrict__ A, const float* __restrict__ W,
                const float* __restrict__ bias, const float* __restrict__ res,
                float* __restrict__ C, int Nw, int K, int ldc, int col_off, int flip)
{
  __shared__ float As[2][128][SROW];
  __shared__ float Bs[2][128][SROW];
  int tid = threadIdx.x;
  int wid = tid >> 5, lane = tid & 31;
  int g = lane >> 2, tg = lane & 3;          // groupID, thread-in-group
  int wm = wid & 1, wn = wid >> 1;           // warp tile: rows wm*64, cols wn*32
  int row0 = blockIdx.y * 128, col0 = blockIdx.x * 128;

  uint32_t sA = (uint32_t)__cvta_generic_to_shared(&As[0][0][0]);
  uint32_t sB = (uint32_t)__cvta_generic_to_shared(&Bs[0][0][0]);
  const uint32_t BUFB = 128 * SROW * 4;

  float acc[4][4][4];
#pragma unroll
  for (int mi = 0; mi < 4; mi++)
#pragma unroll
    for (int ni = 0; ni < 4; ni++)
#pragma unroll
      for (int r = 0; r < 4; r++) acc[mi][ni][r] = 0.f;

  int KT = K / TKS;

  // prologue: load stage 0 into buf 0
  {
    int k0 = 0;
#pragma unroll
    for (int i = 0; i < 2; i++) {
      int idx = tid + i * 256;
      int r = idx >> 2, q = idx & 3;
      cp16(sA + (uint32_t)((r * SROW + q * 4) * 4),
           A + (size_t)(row0 + r) * K + k0 + q * 4, 16);
      int wr = col0 + r;
      const float* ws = W + (size_t)(wr < Nw ? wr : 0) * K + k0 + q * 4;
      cp16(sB + (uint32_t)((r * SROW + q * 4) * 4), ws, (wr < Nw) ? 16 : 0);
    }
    CP_COMMIT();
  }

  for (int kt = 0; kt < KT; kt++) {
    int buf = kt & 1;
    if (kt + 1 < KT) {
      int k0 = (kt + 1) * TKS;
      uint32_t bo = (uint32_t)((buf ^ 1) * BUFB);
#pragma unroll
      for (int i = 0; i < 2; i++) {
        int idx = tid + i * 256;
        int r = idx >> 2, q = idx & 3;
        cp16(sA + bo + (uint32_t)((r * SROW + q * 4) * 4),
             A + (size_t)(row0 + r) * K + k0 + q * 4, 16);
        int wr = col0 + r;
        const float* ws = W + (size_t)(wr < Nw ? wr : 0) * K + k0 + q * 4;
        cp16(sB + bo + (uint32_t)((r * SROW + q * 4) * 4), ws, (wr < Nw) ? 16 : 0);
      }
      CP_COMMIT();
      CP_WAIT1();
    } else {
      CP_WAIT0();
    }
    __syncthreads();

#pragma unroll
    for (int kk = 0; kk < TKS; kk += 8) {
      uint32_t af[4][4], bf[4][2];
#pragma unroll
      for (int mi = 0; mi < 4; mi++) {
        int br = wm * 64 + mi * 16;
        af[mi][0] = __float_as_uint(As[buf][br + g][kk + tg]);
        af[mi][1] = __float_as_uint(As[buf][br + g + 8][kk + tg]);
        af[mi][2] = __float_as_uint(As[buf][br + g][kk + tg + 4]);
        af[mi][3] = __float_as_uint(As[buf][br + g + 8][kk + tg + 4]);
      }
#pragma unroll
      for (int ni = 0; ni < 4; ni++) {
        int bc = wn * 32 + ni * 8;
        bf[ni][0] = __float_as_uint(Bs[buf][bc + g][kk + tg]);
        bf[ni][1] = __float_as_uint(Bs[buf][bc + g][kk + tg + 4]);
      }
#pragma unroll
      for (int mi = 0; mi < 4; mi++)
#pragma unroll
        for (int ni = 0; ni < 4; ni++)
          mma1688(acc[mi][ni], af[mi], bf[ni]);
    }
    __syncthreads();
  }

  // epilogue
#pragma unroll
  for (int mi = 0; mi < 4; mi++) {
#pragma unroll
    for (int half = 0; half < 2; half++) {
      int m = row0 + wm * 64 + mi * 16 + g + half * 8;
      int orow = flip ? ((m & ~2047) + (2047 - (m & 2047))) : m;
      float* crow = C + (size_t)orow * ldc + col_off;
      const float* rrow = res ? (res + (size_t)m * ldc + col_off) : nullptr;
#pragma unroll
      for (int ni = 0; ni < 4; ni++) {
        int n = col0 + wn * 32 + ni * 8 + 2 * tg;
        if (n < Nw) {
          float v0 = acc[mi][ni][half * 2 + 0];
          float v1 = acc[mi][ni][half * 2 + 1];
          if (bias) { v0 += bias[n]; v1 += bias[n + 1]; }
          if (rrow) { v0 += rrow[n]; v1 += rrow[n + 1]; }
          crow[n] = v0; crow[n + 1] = v1;
        }
      }
    }
  }
}

// ---------------- K3: depthwise causal conv(4) + SiLU; softplus(dt), dA ----------------
__global__ __launch_bounds__(256) void k_conv(int dir,
    const float* __restrict__ conv_w, const float* __restrict__ conv_b,
    const float* __restrict__ dt_bias, const float* __restrict__ A_log)
{
  int row = blockIdx.x, tid = threadIdx.x;
  int l = row & 2047, rb = row & ~2047;
  for (int c = tid; c < CONVDIM; c += 256) {
    float acc = conv_b[c];
#pragma unroll
    for (int k = 0; k < 4; k++) {
      int ls = l - 3 + k;
      if (ls >= 0) acc = fmaf(conv_w[c * 4 + k], g_zx[dir][rb + ls][DINNER + c], acc);
    }
    g_xc[dir][row][c] = acc / (1.f + expf(-acc));
  }
  if (tid < NH) {
    float d = g_zx[dir][row][DINNER + CONVDIM + tid] + dt_bias[tid];
    float sp = (d > 20.f) ? d : log1pf(expf(d));
    g_dt[dir][row][tid] = sp;
    g_dA[dir][row][tid] = expf(-sp * expf(A_log[tid]));
  }
}

// ---------------- K4: recurrent scan, both dirs in one launch ----------------
#define TT 32
__global__ __launch_bounds__(512) void k_scan(const float* __restrict__ Df,
                                              const float* __restrict__ Db)
{
  int dir = blockIdx.x >> 5;
  int r = blockIdx.x & 31;
  int b = r >> 4, hh = r & 15;
  int tid = threadIdx.x;
  int p = tid >> 3, g = tid & 7;
  __shared__ float sB[TT][DSTATE];
  __shared__ float sC[TT][DSTATE];
  __shared__ float sx[TT][HD];
  __shared__ float sdt[TT];
  __shared__ float sdA[TT];
  float h[16];
#pragma unroll
  for (int j = 0; j < 16; j++) h[j] = 0.f;
  float Dh = dir ? Db[hh] : Df[hh];
  int rowbase = b << 11;

  for (int t0 = 0; t0 < LSEQ; t0 += TT) {
    __syncthreads();
    for (int i = tid; i < TT * DSTATE; i += 512) {
      int tt = i >> 7, n = i & 127;
      int row = rowbase + t0 + tt;
      sB[tt][n] = g_xc[dir][row][DINNER + n];
      sC[tt][n] = g_xc[dir][row][DINNER + DSTATE + n];
    }
    for (int i = tid; i < TT * HD; i += 512) {
      int tt = i >> 6, pp = i & 63;
      sx[tt][pp] = g_xc[dir][rowbase + t0 + tt][hh * HD + pp];
    }
    if (tid < TT) {
      sdt[tid] = g_dt[dir][rowbase + t0 + tid][hh];
      sdA[tid] = g_dA[dir][rowbase + t0 + tid][hh];
    }
    __syncthreads();
#pragma unroll 4
    for (int tt = 0; tt < TT; tt++) {
      float dA = sdA[tt];
      float s = sdt[tt] * sx[tt][p];
      float acc = 0.f;
#pragma unroll
      for (int j = 0; j < 16; j++) {
        int n = g + (j << 3);
        h[j] = fmaf(dA, h[j], s * sB[tt][n]);
        acc = fmaf(h[j], sC[tt][n], acc);
      }
      acc += __shfl_xor_sync(0xffffffffu, acc, 1);
      acc += __shfl_xor_sync(0xffffffffu, acc, 2);
      acc += __shfl_xor_sync(0xffffffffu, acc, 4);
      if (g == 0)
        g_y[dir][rowbase + t0 + tt][hh * HD + p] = acc + Dh * sx[tt][p];
    }
  }
}

// ---------------- K5: gating + gated RMSNorm ----------------
__global__ __launch_bounds__(256) void k_gate(int dir, const float* __restrict__ gnorm_w)
{
  int row = blockIdx.x, tid = threadIdx.x;
  float vals[4]; float ss = 0.f;
#pragma unroll
  for (int i = 0; i < 4; i++) {
    int c = tid + i * 256;
    float yv = g_y[dir][row][c];
    float z = g_zx[dir][row][c];
    float gv = yv * (z / (1.f + expf(-z)));
    vals[i] = gv; ss += gv * gv;
  }
  __shared__ float red[256];
  red[tid] = ss; __syncthreads();
  for (int s = 128; s > 0; s >>= 1) { if (tid < s) red[tid] += red[tid + s]; __syncthreads(); }
  float sc = rsqrtf(red[0] * (1.f / DINNER) + 1e-5f);
#pragma unroll
  for (int i = 0; i < 4; i++) {
    int c = tid + i * 256;
    g_y[dir][row][c] = vals[i] * sc * gnorm_w[c];
  }
}

// ---------------- launch ----------------
extern "C" void kernel_launch(void* const* d_in, const int* in_sizes, int n_in,
                              void* d_out, int out_size)
{
  (void)in_sizes; (void)n_in; (void)out_size;
  const float* x      = (const float*)d_in[0];
  const float* norm_w = (const float*)d_in[1];
  const float* op_w   = (const float*)d_in[2];
  const float* op_b   = (const float*)d_in[3];
  const float* in_w[2]    = {(const float*)d_in[4],  (const float*)d_in[12]};
  const float* conv_w[2]  = {(const float*)d_in[5],  (const float*)d_in[13]};
  const float* conv_b[2]  = {(const float*)d_in[6],  (const float*)d_in[14]};
  const float* dt_bias[2] = {(const float*)d_in[7],  (const float*)d_in[15]};
  const float* A_log[2]   = {(const float*)d_in[8],  (const float*)d_in[16]};
  const float* Dvec[2]    = {(const float*)d_in[9],  (const float*)d_in[17]};
  const float* gnorm[2]   = {(const float*)d_in[10], (const float*)d_in[18]};
  const float* outp_w[2]  = {(const float*)d_in[11], (const float*)d_in[19]};
  float* out = (float*)d_out;

  float *pu, *pzx, *py, *pod;
  cudaGetSymbolAddress((void**)&pu,  g_u);
  cudaGetSymbolAddress((void**)&pzx, g_zx);
  cudaGetSymbolAddress((void**)&py,  g_y);
  cudaGetSymbolAddress((void**)&pod, g_od);

  k_rmsnorm_split<<<BL, 256>>>(x, norm_w);

  for (int d = 0; d < 2; d++)
    k_gemm_mma<<<dim3((DPROJ + 127) / 128, BL / 128), 256>>>(
        pu + (size_t)d * BL * DHALF, in_w[d], nullptr, nullptr,
        pzx + (size_t)d * BL * DPROJ, DPROJ, DHALF, DPROJ, 0, 0);

  for (int d = 0; d < 2; d++)
    k_conv<<<BL, 256>>>(d, conv_w[d], conv_b[d], dt_bias[d], A_log[d]);

  k_scan<<<64, 512>>>(Dvec[0], Dvec[1]);

  for (int d = 0; d < 2; d++)
    k_gate<<<BL, 256>>>(d, gnorm[d]);

  for (int d = 0; d < 2; d++)
    k_gemm_mma<<<dim3(DHALF / 128, BL / 128), 256>>>(
        py + (size_t)d * BL * DINNER, outp_w[d], nullptr, nullptr,
        pod, DHALF, DINNER, DMODEL, d * DHALF, d);

  k_gemm_mma<<<dim3(DMODEL / 128, BL / 128), 256>>>(
      pod, op_w, op_b, x, out, DMODEL, DMODEL, DMODEL, 0, 0);
}